// round 15
// baseline (speedup 1.0000x reference)
#include <cuda_runtime.h>
#include <cstdint>

#define M_B 128
#define N_F 1024
#define K_F 1024
#define KSPLIT 8
#define BN 64
#define KCHUNK (K_F / KSPLIT)      /* 128 */
#define NBG 16
#define GRID (NBG * KSPLIT)        /* 128 CTAs = 16 clusters x 8 */

#define SA_STRIDE 132              /* conflict-free frag loads */
#define SB_STRIDE 72               /* conflict-free frag loads */
#define SMEM_BYTES ((128 * SA_STRIDE + KCHUNK * SB_STRIDE) * 4)   /* 104448 */

// Scratch (device globals: no allocation allowed in kernel_launch)
__device__ float g_partial[KSPLIT * M_B * N_F];   // 4 MB split-K partials
__device__ float2 g_upart[NBG][KSPLIT][M_B];      // per-cluster u partials

// ---------------------------------------------------------------------------
__device__ __forceinline__ void cp_async16(void* smem, const void* gmem) {
    uint32_t s = (uint32_t)__cvta_generic_to_shared(smem);
    asm volatile("cp.async.cg.shared.global [%0], [%1], 16;\n" :: "r"(s), "l"(gmem));
}
__device__ __forceinline__ void cp_commit() {
    asm volatile("cp.async.commit_group;\n");
}
template <int N>
__device__ __forceinline__ void cp_wait() {
    asm volatile("cp.async.wait_group %0;\n" :: "n"(N));
}
__device__ __forceinline__ uint32_t f2tf32(float x) {
    uint32_t r;
    asm("cvt.rna.tf32.f32 %0, %1;" : "=r"(r) : "f"(x));
    return r;
}

// ---------------------------------------------------------------------------
// ONE kernel, 128 CTAs as 16 clusters of 8 (cluster = nb-group):
//   CTA (nb, ks): monolithic-stage split-K tf32 GEMM tile 128x64 (R12 loop),
//   writes partial slice; computes u-part from resident sA (no extra gmem);
//   cluster barrier (HW, ~380cyc, replay-safe);
//   then reduces its own 8-column slice across the 8 partials + epilogue.
// ---------------------------------------------------------------------------
__global__ __launch_bounds__(256, 1) __cluster_dims__(KSPLIT, 1, 1)
void fused_kernel(
        const float* __restrict__ input,
        const float* __restrict__ weight,
        const float* __restrict__ codes,
        const float* __restrict__ A,
        const float* __restrict__ Bm,
        const float* __restrict__ bias,
        const float* __restrict__ bctx,
        float* __restrict__ out) {
    extern __shared__ float smem[];
    float (*sA)[SA_STRIDE] = reinterpret_cast<float(*)[SA_STRIDE]>(smem);
    float (*sB)[SB_STRIDE] = reinterpret_cast<float(*)[SB_STRIDE]>(smem + 128 * SA_STRIDE);
    __shared__ float s_vd[128][4];

    int tid = threadIdx.x;
    int bid = blockIdx.x;
    int nb_idx = bid >> 3;             // cluster id  (16 groups)
    int ks = bid & 7;                  // rank within cluster
    int nb = nb_idx * BN;
    int k_base = ks * KCHUNK;

    int wid = tid >> 5, lane = tid & 31;
    int wm = wid & 3, wn = wid >> 2;
    int m_base = wm * 32, n_base = wn * 32;
    int g = lane >> 2, q = lane & 3;

    // ---- issue ALL loads for the whole K-chunk (max MLP) ----
    {
        int a_row = tid >> 5, a_c4 = (tid & 31) * 4;
        #pragma unroll
        for (int t = 0; t < 16; t++) {
            int row = a_row + t * 8;
            cp_async16(&sA[row][a_c4], input + row * K_F + k_base + a_c4);
        }
        int b_row = tid >> 4, b_c4 = (tid & 15) * 4;
        #pragma unroll
        for (int t = 0; t < 8; t++) {
            int row = b_row + t * 16;
            cp_async16(&sB[row][b_c4], weight + (k_base + row) * N_F + nb + b_c4);
        }
        cp_commit();
    }

    float acc[2][4][4];
    #pragma unroll
    for (int mi = 0; mi < 2; mi++)
        #pragma unroll
        for (int ni = 0; ni < 4; ni++)
            #pragma unroll
            for (int r = 0; r < 4; r++) acc[mi][ni][r] = 0.f;

    cp_wait<0>();
    __syncthreads();

    // ---- 16 unrolled kk steps, no barriers (proven R12 mainloop) ----
    #pragma unroll
    for (int kk = 0; kk < KCHUNK; kk += 8) {
        uint32_t afr[2][4], bfr[4][2];
        #pragma unroll
        for (int mi = 0; mi < 2; mi++) {
            int r0 = m_base + mi * 16 + g;
            afr[mi][0] = f2tf32(sA[r0    ][kk + q    ]);
            afr[mi][1] = f2tf32(sA[r0 + 8][kk + q    ]);
            afr[mi][2] = f2tf32(sA[r0    ][kk + q + 4]);
            afr[mi][3] = f2tf32(sA[r0 + 8][kk + q + 4]);
        }
        #pragma unroll
        for (int ni = 0; ni < 4; ni++) {
            int c0 = n_base + ni * 8 + g;
            bfr[ni][0] = f2tf32(sB[kk + q    ][c0]);
            bfr[ni][1] = f2tf32(sB[kk + q + 4][c0]);
        }
        #pragma unroll
        for (int mi = 0; mi < 2; mi++)
            #pragma unroll
            for (int ni = 0; ni < 4; ni++) {
                asm volatile(
                    "mma.sync.aligned.m16n8k8.row.col.f32.tf32.tf32.f32 "
                    "{%0,%1,%2,%3}, {%4,%5,%6,%7}, {%8,%9}, {%0,%1,%2,%3};\n"
                    : "+f"(acc[mi][ni][0]), "+f"(acc[mi][ni][1]),
                      "+f"(acc[mi][ni][2]), "+f"(acc[mi][ni][3])
                    : "r"(afr[mi][0]), "r"(afr[mi][1]),
                      "r"(afr[mi][2]), "r"(afr[mi][3]),
                      "r"(bfr[ni][0]), "r"(bfr[ni][1]));
            }
    }

    // ---- write split-K partials ----
    {
        float* part = g_partial + ks * (M_B * N_F);
        #pragma unroll
        for (int mi = 0; mi < 2; mi++)
            #pragma unroll
            for (int ni = 0; ni < 4; ni++) {
                int row = m_base + mi * 16 + g;
                int col = nb + n_base + ni * 8 + q * 2;
                part[row * N_F + col]           = acc[mi][ni][0];
                part[row * N_F + col + 1]       = acc[mi][ni][1];
                part[(row + 8) * N_F + col]     = acc[mi][ni][2];
                part[(row + 8) * N_F + col + 1] = acc[mi][ni][3];
            }
    }

    // ---- u-part for this K-chunk, from resident sA (no extra gmem reads) ----
    {
        int b = tid >> 1, h = tid & 1;
        const float2* A2 = reinterpret_cast<const float2*>(A) + k_base + h * 64;
        const float* ar = &sA[b][h * 64];
        float p0 = 0.f, p1 = 0.f;
        #pragma unroll 8
        for (int i = 0; i < 64; i++) {
            float x = ar[i];
            float2 a = A2[i];
            p0 += x * a.x;
            p1 += x * a.y;
        }
        p0 += __shfl_xor_sync(0xFFFFFFFFu, p0, 1);
        p1 += __shfl_xor_sync(0xFFFFFFFFu, p1, 1);
        if (h == 0) g_upart[nb_idx][ks][b] = make_float2(p0, p1);
    }

    // ---- cluster barrier: orders global stores at cluster scope ----
    __threadfence();
    asm volatile("barrier.cluster.arrive.aligned;" ::: "memory");
    asm volatile("barrier.cluster.wait.aligned;" ::: "memory");

    // ---- v,d for all 128 rows from this cluster's u-parts ----
    if (tid < 128) {
        float u0 = 0.f, u1 = 0.f;
        #pragma unroll
        for (int k = 0; k < KSPLIT; k++) {
            float2 up = g_upart[nb_idx][k][tid];
            u0 += up.x; u1 += up.y;
        }
        float c00 = codes[tid * 4 + 0], c01 = codes[tid * 4 + 1];
        float c10 = codes[tid * 4 + 2], c11 = codes[tid * 4 + 3];
        s_vd[tid][0] = u0 * c00 + u1 * c10;
        s_vd[tid][1] = u0 * c01 + u1 * c11;
        s_vd[tid][2] = c00;
        s_vd[tid][3] = c11;
    }
    __syncthreads();

    // ---- reduce this CTA's 8-column slice + epilogue ----
    {
        int row = tid >> 1;
        int j4 = nb + ks * 8 + (tid & 1) * 4;
        const float* base = &g_partial[row * N_F + j4];
        float4 s = *reinterpret_cast<const float4*>(base);
        #pragma unroll
        for (int k = 1; k < KSPLIT; k++) {
            float4 p = *reinterpret_cast<const float4*>(base + k * (M_B * N_F));
            s.x += p.x; s.y += p.y; s.z += p.z; s.w += p.w;
        }
        float4 bi = *reinterpret_cast<const float4*>(bias + j4);
        float4 B0 = *reinterpret_cast<const float4*>(Bm + j4);
        float4 B1 = *reinterpret_cast<const float4*>(Bm + N_F + j4);
        float4 e0 = *reinterpret_cast<const float4*>(bctx + j4);
        float4 e1 = *reinterpret_cast<const float4*>(bctx + N_F + j4);

        float v0 = s_vd[row][0], v1 = s_vd[row][1];
        float d0 = s_vd[row][2], d1 = s_vd[row][3];
        float4 o;
        o.x = s.x + bi.x + v0 * B0.x + v1 * B1.x + d0 * e0.x + d1 * e1.x;
        o.y = s.y + bi.y + v0 * B0.y + v1 * B1.y + d0 * e0.y + d1 * e1.y;
        o.z = s.z + bi.z + v0 * B0.z + v1 * B1.z + d0 * e0.z + d1 * e1.z;
        o.w = s.w + bi.w + v0 * B0.w + v1 * B1.w + d0 * e0.w + d1 * e1.w;
        *reinterpret_cast<float4*>(out + row * N_F + j4) = o;
    }
}

extern "C" void kernel_launch(void* const* d_in, const int* in_sizes, int n_in,
                              void* d_out, int out_size) {
    const float* input  = (const float*)d_in[0];
    const float* codes  = (const float*)d_in[1];
    const float* weight = (const float*)d_in[2];
    const float* A      = (const float*)d_in[3];
    const float* Bm     = (const float*)d_in[4];
    const float* bias   = (const float*)d_in[5];
    const float* bctx   = (const float*)d_in[6];
    float* out = (float*)d_out;

    cudaFuncSetAttribute(fused_kernel,
                         cudaFuncAttributeMaxDynamicSharedMemorySize, SMEM_BYTES);

    fused_kernel<<<GRID, 256, SMEM_BYTES>>>(input, weight, codes, A,
                                            Bm, bias, bctx, out);
}

// round 16
// speedup vs baseline: 1.6131x; 1.6131x over previous
#include <cuda_runtime.h>
#include <cstdint>

#define M_B 128
#define N_F 1024
#define K_F 1024
#define KSPLIT 16
#define BN 64
#define KCHUNK (K_F / KSPLIT)      /* 64 */
#define GRID 256                   /* 16 nb-groups x 16 ks — 2 CTAs/SM */

#define SA_STRIDE (KCHUNK + 4)     /* 68:  68 mod 32 = 4 -> conflict-free */
#define SB_STRIDE 72               /* conflict-free frag loads */
#define SMEM_BYTES ((128 * SA_STRIDE + KCHUNK * SB_STRIDE) * 4)   /* 53248 */

// Scratch (device globals: no allocation allowed in kernel_launch)
__device__ float g_partial[KSPLIT * M_B * N_F];   // 8 MB split-K partials
__device__ float4 g_vd[M_B];                       // unused spare

// ---------------------------------------------------------------------------
__device__ __forceinline__ void cp_async16(void* smem, const void* gmem) {
    uint32_t s = (uint32_t)__cvta_generic_to_shared(smem);
    asm volatile("cp.async.cg.shared.global [%0], [%1], 16;\n" :: "r"(s), "l"(gmem));
}
__device__ __forceinline__ void cp_commit() {
    asm volatile("cp.async.commit_group;\n");
}
template <int N>
__device__ __forceinline__ void cp_wait() {
    asm volatile("cp.async.wait_group %0;\n" :: "n"(N));
}
__device__ __forceinline__ uint32_t f2tf32(float x) {
    uint32_t r;
    asm("cvt.rna.tf32.f32 %0, %1;" : "=r"(r) : "f"(x));
    return r;
}

// ---------------------------------------------------------------------------
// Kernel 1: split-K tf32 GEMM, monolithic 64-K stage, 2 CTAs/SM.
//   CTA (nb, ks): 128x64 tile of K-chunk ks -> partial slice ks. Nothing else.
// ---------------------------------------------------------------------------
__global__ __launch_bounds__(256, 2) void gemm_kernel(
        const float* __restrict__ input,
        const float* __restrict__ weight) {
    extern __shared__ float smem[];
    float (*sA)[SA_STRIDE] = reinterpret_cast<float(*)[SA_STRIDE]>(smem);
    float (*sB)[SB_STRIDE] = reinterpret_cast<float(*)[SB_STRIDE]>(smem + 128 * SA_STRIDE);

    int tid = threadIdx.x;
    int bid = blockIdx.x;

    int nb = (bid & 15) * BN;
    int ks = bid >> 4;                 // 0..15
    int k_base = ks * KCHUNK;

    int wid = tid >> 5, lane = tid & 31;
    int wm = wid & 3, wn = wid >> 2;
    int m_base = wm * 32, n_base = wn * 32;
    int g = lane >> 2, q = lane & 3;

    // ---- issue ALL loads for the 64-K chunk (12 float4/thread, max MLP) ----
    {
        // sA: 128 rows x 16 f4/row = 2048 f4; 8 per thread
        int a_row = tid >> 4, a_c4 = (tid & 15) * 4;
        #pragma unroll
        for (int t = 0; t < 8; t++) {
            int row = a_row + t * 16;
            cp_async16(&sA[row][a_c4], input + row * K_F + k_base + a_c4);
        }
        // sB: 64 rows x 16 f4/row = 1024 f4; 4 per thread
        int b_row = tid >> 4, b_c4 = (tid & 15) * 4;
        #pragma unroll
        for (int t = 0; t < 4; t++) {
            int row = b_row + t * 16;
            cp_async16(&sB[row][b_c4], weight + (k_base + row) * N_F + nb + b_c4);
        }
        cp_commit();
    }

    float acc[2][4][4];
    #pragma unroll
    for (int mi = 0; mi < 2; mi++)
        #pragma unroll
        for (int ni = 0; ni < 4; ni++)
            #pragma unroll
            for (int r = 0; r < 4; r++) acc[mi][ni][r] = 0.f;

    cp_wait<0>();
    __syncthreads();

    // ---- 8 unrolled kk steps, no barriers ----
    #pragma unroll
    for (int kk = 0; kk < KCHUNK; kk += 8) {
        uint32_t afr[2][4], bfr[4][2];
        #pragma unroll
        for (int mi = 0; mi < 2; mi++) {
            int r0 = m_base + mi * 16 + g;
            afr[mi][0] = f2tf32(sA[r0    ][kk + q    ]);
            afr[mi][1] = f2tf32(sA[r0 + 8][kk + q    ]);
            afr[mi][2] = f2tf32(sA[r0    ][kk + q + 4]);
            afr[mi][3] = f2tf32(sA[r0 + 8][kk + q + 4]);
        }
        #pragma unroll
        for (int ni = 0; ni < 4; ni++) {
            int c0 = n_base + ni * 8 + g;
            bfr[ni][0] = f2tf32(sB[kk + q    ][c0]);
            bfr[ni][1] = f2tf32(sB[kk + q + 4][c0]);
        }
        #pragma unroll
        for (int mi = 0; mi < 2; mi++)
            #pragma unroll
            for (int ni = 0; ni < 4; ni++) {
                asm volatile(
                    "mma.sync.aligned.m16n8k8.row.col.f32.tf32.tf32.f32 "
                    "{%0,%1,%2,%3}, {%4,%5,%6,%7}, {%8,%9}, {%0,%1,%2,%3};\n"
                    : "+f"(acc[mi][ni][0]), "+f"(acc[mi][ni][1]),
                      "+f"(acc[mi][ni][2]), "+f"(acc[mi][ni][3])
                    : "r"(afr[mi][0]), "r"(afr[mi][1]),
                      "r"(afr[mi][2]), "r"(afr[mi][3]),
                      "r"(bfr[ni][0]), "r"(bfr[ni][1]));
            }
    }

    // ---- write split-K partials; kernel ends ----
    float* part = g_partial + ks * (M_B * N_F);
    #pragma unroll
    for (int mi = 0; mi < 2; mi++)
        #pragma unroll
        for (int ni = 0; ni < 4; ni++) {
            int row = m_base + mi * 16 + g;
            int col = nb + n_base + ni * 8 + q * 2;
            part[row * N_F + col]           = acc[mi][ni][0];
            part[row * N_F + col + 1]       = acc[mi][ni][1];
            part[(row + 8) * N_F + col]     = acc[mi][ni][2];
            part[(row + 8) * N_F + col + 1] = acc[mi][ni][3];
        }

    // allow the dependent grid to start its preamble
    asm volatile("griddepcontrol.launch_dependents;");
}

// ---------------------------------------------------------------------------
// Kernel 2 (PDL, R13 structure): preamble = prep + epilogue-vector loads,
// then griddepcontrol.wait, then 16-slice reduce + store.
// ---------------------------------------------------------------------------
__global__ __launch_bounds__(256, 1) void finish_kernel(
        const float* __restrict__ input,
        const float* __restrict__ codes,
        const float* __restrict__ A,
        const float* __restrict__ Bm,
        const float* __restrict__ bias,
        const float* __restrict__ bctx,
        float* __restrict__ out) {
    __shared__ float s_red[8][2];
    int tid = threadIdx.x;
    int b = blockIdx.x;
    int lane = tid & 31, wid = tid >> 5;
    int j4 = tid * 4;

    // ---------- preamble (independent of kernel 1's writes) ----------
    float4 bi = *reinterpret_cast<const float4*>(bias + j4);
    float4 B0 = *reinterpret_cast<const float4*>(Bm + j4);
    float4 B1 = *reinterpret_cast<const float4*>(Bm + N_F + j4);
    float4 e0 = *reinterpret_cast<const float4*>(bctx + j4);
    float4 e1 = *reinterpret_cast<const float4*>(bctx + N_F + j4);

    float v0, v1, d0, d1;
    {
        float4 x = *reinterpret_cast<const float4*>(input + b * K_F + tid * 4);
        const float2* A2 = reinterpret_cast<const float2*>(A);
        float2 a0 = A2[tid * 4 + 0];
        float2 a1 = A2[tid * 4 + 1];
        float2 a2 = A2[tid * 4 + 2];
        float2 a3 = A2[tid * 4 + 3];
        float p0 = x.x * a0.x + x.y * a1.x + x.z * a2.x + x.w * a3.x;
        float p1 = x.x * a0.y + x.y * a1.y + x.z * a2.y + x.w * a3.y;
        #pragma unroll
        for (int off = 16; off > 0; off >>= 1) {
            p0 += __shfl_xor_sync(0xFFFFFFFFu, p0, off);
            p1 += __shfl_xor_sync(0xFFFFFFFFu, p1, off);
        }
        if (lane == 0) { s_red[wid][0] = p0; s_red[wid][1] = p1; }
        __syncthreads();
        float u0 = 0.f, u1 = 0.f;
        #pragma unroll
        for (int i = 0; i < 8; i++) { u0 += s_red[i][0]; u1 += s_red[i][1]; }
        float c00 = codes[b * 4 + 0], c01 = codes[b * 4 + 1];
        float c10 = codes[b * 4 + 2], c11 = codes[b * 4 + 3];
        v0 = u0 * c00 + u1 * c10;
        v1 = u0 * c01 + u1 * c11;
        d0 = c00;
        d1 = c11;
    }

    // ---------- wait for upstream grid's stores to be visible ----------
    asm volatile("griddepcontrol.wait;" ::: "memory");

    // ---------- 16-slice reduce (independent float4 chains, MLP-16) ----------
    const float* base = &g_partial[b * N_F + j4];
    float4 s = *reinterpret_cast<const float4*>(base);
    #pragma unroll
    for (int k = 1; k < KSPLIT; k++) {
        float4 p = *reinterpret_cast<const float4*>(base + k * (M_B * N_F));
        s.x += p.x; s.y += p.y; s.z += p.z; s.w += p.w;
    }

    float4 o;
    o.x = s.x + bi.x + v0 * B0.x + v1 * B1.x + d0 * e0.x + d1 * e1.x;
    o.y = s.y + bi.y + v0 * B0.y + v1 * B1.y + d0 * e0.y + d1 * e1.y;
    o.z = s.z + bi.z + v0 * B0.z + v1 * B1.z + d0 * e0.z + d1 * e1.z;
    o.w = s.w + bi.w + v0 * B0.w + v1 * B1.w + d0 * e0.w + d1 * e1.w;
    *reinterpret_cast<float4*>(out + b * N_F + j4) = o;
}

extern "C" void kernel_launch(void* const* d_in, const int* in_sizes, int n_in,
                              void* d_out, int out_size) {
    const float* input  = (const float*)d_in[0];
    const float* codes  = (const float*)d_in[1];
    const float* weight = (const float*)d_in[2];
    const float* A      = (const float*)d_in[3];
    const float* Bm     = (const float*)d_in[4];
    const float* bias   = (const float*)d_in[5];
    const float* bctx   = (const float*)d_in[6];
    float* out = (float*)d_out;

    cudaFuncSetAttribute(gemm_kernel,
                         cudaFuncAttributeMaxDynamicSharedMemorySize, SMEM_BYTES);

    gemm_kernel<<<GRID, 256, SMEM_BYTES>>>(input, weight);

    // finish_kernel with programmatic dependent launch (overlaps gemm tail)
    cudaLaunchConfig_t cfg = {};
    cfg.gridDim = dim3(M_B);
    cfg.blockDim = dim3(256);
    cfg.dynamicSmemBytes = 0;
    cfg.stream = 0;
    cudaLaunchAttribute at[1];
    at[0].id = cudaLaunchAttributeProgrammaticStreamSerialization;
    at[0].val.programmaticStreamSerializationAllowed = 1;
    cfg.attrs = at;
    cfg.numAttrs = 1;
    cudaLaunchKernelEx(&cfg, finish_kernel, input, codes, A, Bm, bias, bctx, out);
}